// round 1
// baseline (speedup 1.0000x reference)
#include <cuda_runtime.h>
#include <math.h>

// ---------------- static problem config ----------------
#define PT     144          // tokens per window
#define DIMV   192
#define HEADS  6
#define DH     32
#define WNUM   960          // total windows (B=1)
#define MWIN   15           // MW
#define WTYPES 64           // MZ*MH
#define MROWS  (WNUM*PT)    // 138240
#define QK_SCALE 0.17677669529663687f   // 32^-0.5

// ---------------- device scratch (allocation-free rule) ----------------
__device__ float g_q [WNUM*HEADS*PT*DH];   // (wn, h, p, d)
__device__ float g_k [WNUM*HEADS*PT*DH];
__device__ float g_v [WNUM*HEADS*PT*DH];
__device__ float g_ao[MROWS*DIMV];         // attention output, (wn*P+p, dim)
__device__ float g_bias[WTYPES*HEADS*PT*PT];

// =====================================================================
// Kernel 1: QKV GEMM  C(138240,576) = x(138240,192) @ w_qkv(192,576)
// tile 128x64, BK=16, 256 threads, 8x4 per-thread microtile.
// Epilogue scatters into g_q/g_k/g_v layouts (q scaled).
// =====================================================================
__global__ __launch_bounds__(256) void qkv_gemm(const float* __restrict__ x,
                                                const float* __restrict__ w)
{
    __shared__ float As[16][129];   // [k][m], pad 129 -> conflict-free stores
    __shared__ float Bs[16][64];

    const int m0  = blockIdx.x * 128;
    const int n0  = blockIdx.y * 64;
    const int tid = threadIdx.x;
    const int tx  = tid & 15;
    const int ty  = tid >> 4;

    float acc[8][4];
    #pragma unroll
    for (int r = 0; r < 8; r++)
        #pragma unroll
        for (int c = 0; c < 4; c++) acc[r][c] = 0.f;

    const int arow = tid >> 2;          // 0..63
    const int akq  = (tid & 3) * 4;     // 0,4,8,12
    const int bk   = tid >> 4;          // 0..15
    const int bn   = (tid & 15) * 4;    // 0..60

    for (int kt = 0; kt < 192; kt += 16) {
        #pragma unroll
        for (int i = 0; i < 2; i++) {
            const int row = arow + i * 64;
            float4 a = *(const float4*)(x + (size_t)(m0 + row) * 192 + kt + akq);
            As[akq + 0][row] = a.x;
            As[akq + 1][row] = a.y;
            As[akq + 2][row] = a.z;
            As[akq + 3][row] = a.w;
        }
        {
            float4 b = *(const float4*)(w + (size_t)(kt + bk) * 576 + n0 + bn);
            *(float4*)&Bs[bk][bn] = b;
        }
        __syncthreads();

        #pragma unroll
        for (int k = 0; k < 16; k++) {
            float a[8];
            #pragma unroll
            for (int r = 0; r < 8; r++) a[r] = As[k][ty * 8 + r];
            float4 b4 = *(const float4*)&Bs[k][tx * 4];
            float b[4] = {b4.x, b4.y, b4.z, b4.w};
            #pragma unroll
            for (int r = 0; r < 8; r++)
                #pragma unroll
                for (int c = 0; c < 4; c++) acc[r][c] += a[r] * b[c];
        }
        __syncthreads();
    }

    // scatter epilogue
    #pragma unroll
    for (int r = 0; r < 8; r++) {
        const int m  = m0 + ty * 8 + r;
        const int wn = m / PT;
        const int p  = m - wn * PT;
        #pragma unroll
        for (int c = 0; c < 4; c++) {
            const int n     = n0 + tx * 4 + c;
            const int three = n / 192;
            const int rem   = n - three * 192;
            const int head  = rem >> 5;
            const int d     = rem & 31;
            float v = acc[r][c];
            const size_t di = (((size_t)wn * HEADS + head) * PT + p) * DH + d;
            if (three == 0)      g_q[di] = v * QK_SCALE;
            else if (three == 1) g_k[di] = v;
            else                 g_v[di] = v;
        }
    }
}

// =====================================================================
// Kernel 2: earth-bias gather into contiguous (WT, H, P, P)
// =====================================================================
__global__ void bias_kernel(const float* __restrict__ table)
{
    int t = blockIdx.x * 256 + threadIdx.x;
    if (t >= WTYPES * HEADS * PT * PT) return;
    int j  = t % PT;
    int r1 = t / PT;
    int i  = r1 % PT;
    int r2 = r1 / PT;
    int h  = r2 % HEADS;
    int wt = r2 / HEADS;

    int zi = i / 72, hi = (i / 12) % 6, wi = i % 12;
    int zj = j / 72, hj = (j / 12) % 6, wj = j % 12;
    int idx = 828 * (zi + 2 * zj) + 23 * (hi + 6 * hj) + (wi - wj + 11);

    g_bias[t] = table[(size_t)idx * (WTYPES * HEADS) + wt * HEADS + h];
}

// =====================================================================
// Kernel 3: attention per (window, head). 256 threads, ~137KB smem.
//   phase1: S = Q K^T via 9x9 register microtiles
//   phase2: S += bias + mask; row softmax (warp per row)
//   phase3: O = S V (3-row register blocking), write to g_ao
// =====================================================================
#define ATTN_SMEM ((3*PT*33 + PT*PT) * 4)   // 139,968 bytes

__global__ __launch_bounds__(256) void attn_kernel(const float* __restrict__ mask)
{
    extern __shared__ float sm[];
    float* Qs = sm;                 // 144*33
    float* Ks = sm + PT * 33;
    float* Vs = sm + 2 * PT * 33;
    float* Ss = sm + 3 * PT * 33;   // 144*144

    const int wn  = blockIdx.x / HEADS;
    const int h   = blockIdx.x - wn * HEADS;
    const int tid = threadIdx.x;

    const size_t base = ((size_t)wn * HEADS + h) * (PT * DH);
    for (int i = tid; i < PT * DH; i += 256) {
        int r = i >> 5, d = i & 31;
        Qs[r * 33 + d] = g_q[base + i];
        Ks[r * 33 + d] = g_k[base + i];
        Vs[r * 33 + d] = g_v[base + i];
    }
    __syncthreads();

    // ---- phase 1: S = Q K^T ----
    {
        const int tx = tid & 15, ty = tid >> 4;
        float acc[9][9];
        #pragma unroll
        for (int r = 0; r < 9; r++)
            #pragma unroll
            for (int c = 0; c < 9; c++) acc[r][c] = 0.f;

        const float* qp = Qs + (ty * 9) * 33;
        const float* kp = Ks + (tx * 9) * 33;

        #pragma unroll 4
        for (int d = 0; d < DH; d++) {
            float qv[9], kv[9];
            #pragma unroll
            for (int r = 0; r < 9; r++) qv[r] = qp[r * 33 + d];
            #pragma unroll
            for (int c = 0; c < 9; c++) kv[c] = kp[c * 33 + d];
            #pragma unroll
            for (int r = 0; r < 9; r++)
                #pragma unroll
                for (int c = 0; c < 9; c++) acc[r][c] += qv[r] * kv[c];
        }

        #pragma unroll
        for (int r = 0; r < 9; r++)
            #pragma unroll
            for (int c = 0; c < 9; c++)
                Ss[(ty * 9 + r) * PT + tx * 9 + c] = acc[r][c];
    }
    __syncthreads();

    // ---- phase 2: bias + mask + softmax (warp per row) ----
    {
        const int w    = tid >> 5;
        const int lane = tid & 31;
        const int wt   = wn / MWIN;
        const float* bp = g_bias + ((size_t)(wt * HEADS + h)) * PT * PT;
        const float* mp = mask + (size_t)wn * PT * PT;

        for (int i = w; i < PT; i += 8) {
            float vals[5];
            float mx = -1e30f;
            #pragma unroll
            for (int c = 0; c < 5; c++) {
                int j = lane + c * 32;
                float v = -1e30f;
                if (j < PT) v = Ss[i * PT + j] + bp[i * PT + j] + mp[i * PT + j];
                vals[c] = v;
                mx = fmaxf(mx, v);
            }
            #pragma unroll
            for (int o = 16; o; o >>= 1) mx = fmaxf(mx, __shfl_xor_sync(0xffffffffu, mx, o));
            float s = 0.f;
            #pragma unroll
            for (int c = 0; c < 5; c++) {
                int j = lane + c * 32;
                float e = (j < PT) ? __expf(vals[c] - mx) : 0.f;
                vals[c] = e;
                s += e;
            }
            #pragma unroll
            for (int o = 16; o; o >>= 1) s += __shfl_xor_sync(0xffffffffu, s, o);
            float inv = 1.f / s;
            #pragma unroll
            for (int c = 0; c < 5; c++) {
                int j = lane + c * 32;
                if (j < PT) Ss[i * PT + j] = vals[c] * inv;
            }
        }
    }
    __syncthreads();

    // ---- phase 3: O = S V ----
    {
        const int w    = tid >> 5;
        const int lane = tid & 31;
        #pragma unroll
        for (int g = 0; g < 6; g++) {
            const int i0 = w + 8 * (3 * g);
            const int i1 = i0 + 8;
            const int i2 = i0 + 16;
            float o0 = 0.f, o1 = 0.f, o2 = 0.f;
            const float* s0 = Ss + i0 * PT;
            const float* s1 = Ss + i1 * PT;
            const float* s2 = Ss + i2 * PT;
            #pragma unroll 4
            for (int j = 0; j < PT; j++) {
                float vv = Vs[j * 33 + lane];
                o0 += s0[j] * vv;
                o1 += s1[j] * vv;
                o2 += s2[j] * vv;
            }
            const size_t col = (size_t)h * DH + lane;
            g_ao[((size_t)(wn * PT + i0)) * DIMV + col] = o0;
            g_ao[((size_t)(wn * PT + i1)) * DIMV + col] = o1;
            g_ao[((size_t)(wn * PT + i2)) * DIMV + col] = o2;
        }
    }
}

// =====================================================================
// Kernel 4: proj GEMM  out(138240,192) = g_ao @ w_proj(192,192) + b_proj
// =====================================================================
__global__ __launch_bounds__(256) void proj_gemm(const float* __restrict__ w,
                                                 const float* __restrict__ bias,
                                                 float* __restrict__ out)
{
    __shared__ float As[16][129];
    __shared__ float Bs[16][64];

    const int m0  = blockIdx.x * 128;
    const int n0  = blockIdx.y * 64;
    const int tid = threadIdx.x;
    const int tx  = tid & 15;
    const int ty  = tid >> 4;

    float acc[8][4];
    #pragma unroll
    for (int r = 0; r < 8; r++)
        #pragma unroll
        for (int c = 0; c < 4; c++) acc[r][c] = 0.f;

    const int arow = tid >> 2;
    const int akq  = (tid & 3) * 4;
    const int bk   = tid >> 4;
    const int bn   = (tid & 15) * 4;

    for (int kt = 0; kt < 192; kt += 16) {
        #pragma unroll
        for (int i = 0; i < 2; i++) {
            const int row = arow + i * 64;
            float4 a = *(const float4*)(g_ao + (size_t)(m0 + row) * 192 + kt + akq);
            As[akq + 0][row] = a.x;
            As[akq + 1][row] = a.y;
            As[akq + 2][row] = a.z;
            As[akq + 3][row] = a.w;
        }
        {
            float4 b = *(const float4*)(w + (size_t)(kt + bk) * 192 + n0 + bn);
            *(float4*)&Bs[bk][bn] = b;
        }
        __syncthreads();

        #pragma unroll
        for (int k = 0; k < 16; k++) {
            float a[8];
            #pragma unroll
            for (int r = 0; r < 8; r++) a[r] = As[k][ty * 8 + r];
            float4 b4 = *(const float4*)&Bs[k][tx * 4];
            float b[4] = {b4.x, b4.y, b4.z, b4.w};
            #pragma unroll
            for (int r = 0; r < 8; r++)
                #pragma unroll
                for (int c = 0; c < 4; c++) acc[r][c] += a[r] * b[c];
        }
        __syncthreads();
    }

    float4 bp = *(const float4*)(bias + n0 + tx * 4);
    #pragma unroll
    for (int r = 0; r < 8; r++) {
        const int m = m0 + ty * 8 + r;
        float4 o;
        o.x = acc[r][0] + bp.x;
        o.y = acc[r][1] + bp.y;
        o.z = acc[r][2] + bp.z;
        o.w = acc[r][3] + bp.w;
        *(float4*)(out + (size_t)m * 192 + n0 + tx * 4) = o;
    }
}

// =====================================================================
extern "C" void kernel_launch(void* const* d_in, const int* in_sizes, int n_in,
                              void* d_out, int out_size)
{
    const float* x          = (const float*)d_in[0];
    const float* mask       = (const float*)d_in[1];
    const float* w_qkv      = (const float*)d_in[2];
    const float* w_proj     = (const float*)d_in[3];
    const float* b_proj     = (const float*)d_in[4];
    const float* bias_table = (const float*)d_in[5];
    float* out = (float*)d_out;

    cudaFuncSetAttribute(attn_kernel,
                         cudaFuncAttributeMaxDynamicSharedMemorySize, ATTN_SMEM);

    dim3 g1(MROWS / 128, 576 / 64);
    qkv_gemm<<<g1, 256>>>(x, w_qkv);

    bias_kernel<<<(WTYPES * HEADS * PT * PT + 255) / 256, 256>>>(bias_table);

    attn_kernel<<<WNUM * HEADS, 256, ATTN_SMEM>>>(mask);

    dim3 g2(MROWS / 128, 192 / 64);
    proj_gemm<<<g2, 256>>>(w_proj, b_proj, out);
}

// round 2
// speedup vs baseline: 1.4471x; 1.4471x over previous
#include <cuda_runtime.h>
#include <math.h>

// ---------------- static problem config ----------------
#define PT     144          // tokens per window
#define DIMV   192
#define HEADS  6
#define DH     32
#define WNUM   960          // total windows (B=1)
#define MWIN   15           // MW
#define WTYPES 64           // MZ*MH
#define MROWS  (WNUM*PT)    // 138240
#define QK_SCALE 0.17677669529663687f   // 32^-0.5

// ---------------- device scratch (allocation-free rule) ----------------
__device__ float g_q [WNUM*HEADS*PT*DH];   // (wn, h, p, d)
__device__ float g_k [WNUM*HEADS*PT*DH];
__device__ float g_v [WNUM*HEADS*PT*DH];
__device__ float g_ao[MROWS*DIMV];         // attention output, (wn*P+p, dim)
__device__ float g_bias[WTYPES*HEADS*PT*PT];

// ---------------- tf32 helpers ----------------
__device__ __forceinline__ float f2tf(float f) {
    unsigned r;
    asm("cvt.rna.tf32.f32 %0, %1;" : "=r"(r) : "f"(f));
    return __uint_as_float(r);
}

__device__ __forceinline__ void mma_tf32(float c[4],
                                         float a0, float a1, float a2, float a3,
                                         float b0, float b1)
{
    unsigned const ua0 = __float_as_uint(a0), ua1 = __float_as_uint(a1);
    unsigned const ua2 = __float_as_uint(a2), ua3 = __float_as_uint(a3);
    unsigned const ub0 = __float_as_uint(b0), ub1 = __float_as_uint(b1);
    asm volatile(
        "mma.sync.aligned.m16n8k8.row.col.f32.tf32.tf32.f32 "
        "{%0,%1,%2,%3}, {%4,%5,%6,%7}, {%8,%9}, {%0,%1,%2,%3};"
        : "+f"(c[0]), "+f"(c[1]), "+f"(c[2]), "+f"(c[3])
        : "r"(ua0), "r"(ua1), "r"(ua2), "r"(ua3), "r"(ub0), "r"(ub1));
}

// =====================================================================
// Kernel 1: QKV GEMM (tf32 tensor core)
// C(138240,576) = x(138240,192) @ w_qkv(192,576); scatter epilogue.
// Block tile 128x64, BK=32, 256 thr / 8 warps (4x2), warp tile 32x32.
// =====================================================================
__global__ __launch_bounds__(256) void qkv_gemm(const float* __restrict__ x,
                                                const float* __restrict__ w)
{
    __shared__ float As[128][36];   // [m][k], stride 36 -> conflict-free A frags
    __shared__ float Bs[32][72];    // [k][n], stride 72 -> conflict-free B frags

    const int m0  = blockIdx.x * 128;
    const int n0  = blockIdx.y * 64;
    const int tid = threadIdx.x;
    const int wid  = tid >> 5;
    const int lane = tid & 31;
    const int grp  = lane >> 2;
    const int tig  = lane & 3;
    const int wm = (wid >> 1) * 32;
    const int wn = (wid & 1) * 32;

    float acc[2][4][4];
    #pragma unroll
    for (int mt = 0; mt < 2; mt++)
        #pragma unroll
        for (int nt = 0; nt < 4; nt++)
            #pragma unroll
            for (int i = 0; i < 4; i++) acc[mt][nt][i] = 0.f;

    const int arow = tid >> 3;          // 0..31
    const int akq  = (tid & 7) * 4;     // 0..28
    const int brow = tid >> 3;          // 0..31
    const int bnq  = (tid & 7) * 8;     // 0..56

    for (int kt = 0; kt < 192; kt += 32) {
        #pragma unroll
        for (int i = 0; i < 4; i++) {
            const int row = arow + i * 32;
            float4 a = *(const float4*)(x + (size_t)(m0 + row) * 192 + kt + akq);
            As[row][akq + 0] = f2tf(a.x);
            As[row][akq + 1] = f2tf(a.y);
            As[row][akq + 2] = f2tf(a.z);
            As[row][akq + 3] = f2tf(a.w);
        }
        #pragma unroll
        for (int i = 0; i < 2; i++) {
            float4 b = *(const float4*)(w + (size_t)(kt + brow) * 576 + n0 + bnq + i * 4);
            Bs[brow][bnq + i*4 + 0] = f2tf(b.x);
            Bs[brow][bnq + i*4 + 1] = f2tf(b.y);
            Bs[brow][bnq + i*4 + 2] = f2tf(b.z);
            Bs[brow][bnq + i*4 + 3] = f2tf(b.w);
        }
        __syncthreads();

        #pragma unroll
        for (int ks = 0; ks < 4; ks++) {
            const int k0 = ks * 8;
            float a[2][4];
            #pragma unroll
            for (int mt = 0; mt < 2; mt++) {
                const int Rm = wm + mt * 16 + grp;
                a[mt][0] = As[Rm][k0 + tig];
                a[mt][1] = As[Rm + 8][k0 + tig];
                a[mt][2] = As[Rm][k0 + tig + 4];
                a[mt][3] = As[Rm + 8][k0 + tig + 4];
            }
            float b[4][2];
            #pragma unroll
            for (int nt = 0; nt < 4; nt++) {
                const int Cn = wn + nt * 8 + grp;
                b[nt][0] = Bs[k0 + tig][Cn];
                b[nt][1] = Bs[k0 + tig + 4][Cn];
            }
            #pragma unroll
            for (int mt = 0; mt < 2; mt++)
                #pragma unroll
                for (int nt = 0; nt < 4; nt++)
                    mma_tf32(acc[mt][nt], a[mt][0], a[mt][1], a[mt][2], a[mt][3],
                             b[nt][0], b[nt][1]);
        }
        __syncthreads();
    }

    // scatter epilogue (float2 pairs, cols 2*tig / 2*tig+1 share head & segment)
    #pragma unroll
    for (int mt = 0; mt < 2; mt++) {
        #pragma unroll
        for (int half = 0; half < 2; half++) {
            const int m  = m0 + wm + mt * 16 + grp + half * 8;
            const int wnn = m / PT;
            const int p   = m - wnn * PT;
            #pragma unroll
            for (int nt = 0; nt < 4; nt++) {
                const int n     = n0 + wn + nt * 8 + 2 * tig;
                const int three = n / 192;
                const int rem   = n - three * 192;
                const int head  = rem >> 5;
                const int d     = rem & 31;
                float v0 = acc[mt][nt][half * 2 + 0];
                float v1 = acc[mt][nt][half * 2 + 1];
                const size_t di = (((size_t)wnn * HEADS + head) * PT + p) * DH + d;
                if (three == 0) {
                    *(float2*)(g_q + di) = make_float2(v0 * QK_SCALE, v1 * QK_SCALE);
                } else if (three == 1) {
                    *(float2*)(g_k + di) = make_float2(v0, v1);
                } else {
                    *(float2*)(g_v + di) = make_float2(v0, v1);
                }
            }
        }
    }
}

// =====================================================================
// Kernel 2: earth-bias gather into contiguous (WT, H, P, P)
// =====================================================================
__global__ void bias_kernel(const float* __restrict__ table)
{
    int t = blockIdx.x * 256 + threadIdx.x;
    if (t >= WTYPES * HEADS * PT * PT) return;
    int j  = t % PT;
    int r1 = t / PT;
    int i  = r1 % PT;
    int r2 = r1 / PT;
    int h  = r2 % HEADS;
    int wt = r2 / HEADS;

    int zi = i / 72, hi = (i / 12) % 6, wi = i % 12;
    int zj = j / 72, hj = (j / 12) % 6, wj = j % 12;
    int idx = 828 * (zi + 2 * zj) + 23 * (hi + 6 * hj) + (wi - wj + 11);

    g_bias[t] = table[(size_t)idx * (WTYPES * HEADS) + wt * HEADS + h];
}

// =====================================================================
// Kernel 3: attention per (window, head), tf32 tensor core.
// 288 threads / 9 warps.
//   phase1: S = Q K^T (warp tile 48x48, K=32)
//   phase2: bias + mask + softmax (fp32), writeback tf32-rounded
//   phase3: O = S V (warp tile 16x32, K=144)
// V reuses the Q buffer after phase 1.
// smem: 2*144*36 + 144*148 floats = 126720 B
// =====================================================================
#define ATTN_SMEM ((2*PT*36 + PT*148) * 4)

__global__ __launch_bounds__(288) void attn_kernel(const float* __restrict__ mask)
{
    extern __shared__ float sm[];
    float* Qs = sm;                 // 144*36  (V after phase 1)
    float* Ks = sm + PT * 36;
    float* Ss = sm + 2 * PT * 36;   // 144*148

    const int wn  = blockIdx.x / HEADS;
    const int h   = blockIdx.x - wn * HEADS;
    const int tid  = threadIdx.x;
    const int wid  = tid >> 5;
    const int lane = tid & 31;
    const int grp  = lane >> 2;
    const int tig  = lane & 3;

    const size_t base = ((size_t)wn * HEADS + h) * (PT * DH);
    for (int i = tid; i < PT * DH; i += 288) {
        int r = i >> 5, d = i & 31;
        Qs[r * 36 + d] = f2tf(g_q[base + i]);
        Ks[r * 36 + d] = f2tf(g_k[base + i]);
    }
    __syncthreads();

    // ---- phase 1: S = Q K^T ----
    {
        const int wm = (wid / 3) * 48;
        const int wq = (wid % 3) * 48;
        float acc[3][6][4];
        #pragma unroll
        for (int mt = 0; mt < 3; mt++)
            #pragma unroll
            for (int nt = 0; nt < 6; nt++)
                #pragma unroll
                for (int i = 0; i < 4; i++) acc[mt][nt][i] = 0.f;

        #pragma unroll
        for (int ks = 0; ks < 4; ks++) {
            const int k0 = ks * 8;
            float a[3][4];
            #pragma unroll
            for (int mt = 0; mt < 3; mt++) {
                const int Rm = wm + mt * 16 + grp;
                a[mt][0] = Qs[Rm * 36 + k0 + tig];
                a[mt][1] = Qs[(Rm + 8) * 36 + k0 + tig];
                a[mt][2] = Qs[Rm * 36 + k0 + tig + 4];
                a[mt][3] = Qs[(Rm + 8) * 36 + k0 + tig + 4];
            }
            float b[6][2];
            #pragma unroll
            for (int nt = 0; nt < 6; nt++) {
                const int Rn = wq + nt * 8 + grp;
                b[nt][0] = Ks[Rn * 36 + k0 + tig];
                b[nt][1] = Ks[Rn * 36 + k0 + tig + 4];
            }
            #pragma unroll
            for (int mt = 0; mt < 3; mt++)
                #pragma unroll
                for (int nt = 0; nt < 6; nt++)
                    mma_tf32(acc[mt][nt], a[mt][0], a[mt][1], a[mt][2], a[mt][3],
                             b[nt][0], b[nt][1]);
        }

        #pragma unroll
        for (int mt = 0; mt < 3; mt++)
            #pragma unroll
            for (int nt = 0; nt < 6; nt++) {
                const int r0 = wm + mt * 16 + grp;
                const int c0 = wq + nt * 8 + 2 * tig;
                Ss[r0 * 148 + c0]       = acc[mt][nt][0];
                Ss[r0 * 148 + c0 + 1]   = acc[mt][nt][1];
                Ss[(r0+8) * 148 + c0]   = acc[mt][nt][2];
                Ss[(r0+8) * 148 + c0+1] = acc[mt][nt][3];
            }
    }
    __syncthreads();

    // ---- load V into the Q buffer (phase 1 done with Qs) ----
    for (int i = tid; i < PT * DH; i += 288) {
        int r = i >> 5, d = i & 31;
        Qs[r * 36 + d] = f2tf(g_v[base + i]);
    }

    // ---- phase 2: bias + mask + softmax (warp per row) ----
    {
        const int wt = wn / MWIN;
        const float* bp = g_bias + ((size_t)(wt * HEADS + h)) * PT * PT;
        const float* mp = mask + (size_t)wn * PT * PT;

        for (int i = wid; i < PT; i += 9) {
            float vals[5];
            float mx = -1e30f;
            #pragma unroll
            for (int c = 0; c < 5; c++) {
                int j = lane + c * 32;
                float v = -1e30f;
                if (j < PT) v = Ss[i * 148 + j] + bp[i * PT + j] + mp[i * PT + j];
                vals[c] = v;
                mx = fmaxf(mx, v);
            }
            #pragma unroll
            for (int o = 16; o; o >>= 1) mx = fmaxf(mx, __shfl_xor_sync(0xffffffffu, mx, o));
            float s = 0.f;
            #pragma unroll
            for (int c = 0; c < 5; c++) {
                int j = lane + c * 32;
                float e = (j < PT) ? __expf(vals[c] - mx) : 0.f;
                vals[c] = e;
                s += e;
            }
            #pragma unroll
            for (int o = 16; o; o >>= 1) s += __shfl_xor_sync(0xffffffffu, s, o);
            float inv = 1.f / s;
            #pragma unroll
            for (int c = 0; c < 5; c++) {
                int j = lane + c * 32;
                if (j < PT) Ss[i * 148 + j] = f2tf(vals[c] * inv);
            }
        }
    }
    __syncthreads();

    // ---- phase 3: O = S V  (warp tile 16x32, K=144) ----
    {
        const int m0 = wid * 16;
        float acc[4][4];
        #pragma unroll
        for (int nt = 0; nt < 4; nt++)
            #pragma unroll
            for (int i = 0; i < 4; i++) acc[nt][i] = 0.f;

        #pragma unroll 2
        for (int k0 = 0; k0 < PT; k0 += 8) {
            float a0 = Ss[(m0 + grp) * 148 + k0 + tig];
            float a1 = Ss[(m0 + 8 + grp) * 148 + k0 + tig];
            float a2 = Ss[(m0 + grp) * 148 + k0 + tig + 4];
            float a3 = Ss[(m0 + 8 + grp) * 148 + k0 + tig + 4];
            float b[4][2];
            #pragma unroll
            for (int nt = 0; nt < 4; nt++) {
                const int n = nt * 8 + grp;
                b[nt][0] = Qs[(k0 + tig) * 36 + n];
                b[nt][1] = Qs[(k0 + tig + 4) * 36 + n];
            }
            #pragma unroll
            for (int nt = 0; nt < 4; nt++)
                mma_tf32(acc[nt], a0, a1, a2, a3, b[nt][0], b[nt][1]);
        }

        #pragma unroll
        for (int half = 0; half < 2; half++) {
            const int row = m0 + grp + half * 8;
            float* op = g_ao + ((size_t)(wn * PT + row)) * DIMV + h * DH;
            #pragma unroll
            for (int nt = 0; nt < 4; nt++) {
                const int col = nt * 8 + 2 * tig;
                *(float2*)(op + col) = make_float2(acc[nt][half*2], acc[nt][half*2+1]);
            }
        }
    }
}

// =====================================================================
// Kernel 4: proj GEMM (tf32)  out(138240,192) = g_ao @ w_proj + b_proj
// =====================================================================
__global__ __launch_bounds__(256) void proj_gemm(const float* __restrict__ w,
                                                 const float* __restrict__ bias,
                                                 float* __restrict__ out)
{
    __shared__ float As[128][36];
    __shared__ float Bs[32][72];

    const int m0  = blockIdx.x * 128;
    const int n0  = blockIdx.y * 64;
    const int tid = threadIdx.x;
    const int wid  = tid >> 5;
    const int lane = tid & 31;
    const int grp  = lane >> 2;
    const int tig  = lane & 3;
    const int wm = (wid >> 1) * 32;
    const int wn = (wid & 1) * 32;

    float acc[2][4][4];
    #pragma unroll
    for (int mt = 0; mt < 2; mt++)
        #pragma unroll
        for (int nt = 0; nt < 4; nt++)
            #pragma unroll
            for (int i = 0; i < 4; i++) acc[mt][nt][i] = 0.f;

    const int arow = tid >> 3;
    const int akq  = (tid & 7) * 4;
    const int brow = tid >> 3;
    const int bnq  = (tid & 7) * 8;

    for (int kt = 0; kt < 192; kt += 32) {
        #pragma unroll
        for (int i = 0; i < 4; i++) {
            const int row = arow + i * 32;
            float4 a = *(const float4*)(g_ao + (size_t)(m0 + row) * 192 + kt + akq);
            As[row][akq + 0] = f2tf(a.x);
            As[row][akq + 1] = f2tf(a.y);
            As[row][akq + 2] = f2tf(a.z);
            As[row][akq + 3] = f2tf(a.w);
        }
        #pragma unroll
        for (int i = 0; i < 2; i++) {
            float4 b = *(const float4*)(w + (size_t)(kt + brow) * 192 + n0 + bnq + i * 4);
            Bs[brow][bnq + i*4 + 0] = f2tf(b.x);
            Bs[brow][bnq + i*4 + 1] = f2tf(b.y);
            Bs[brow][bnq + i*4 + 2] = f2tf(b.z);
            Bs[brow][bnq + i*4 + 3] = f2tf(b.w);
        }
        __syncthreads();

        #pragma unroll
        for (int ks = 0; ks < 4; ks++) {
            const int k0 = ks * 8;
            float a[2][4];
            #pragma unroll
            for (int mt = 0; mt < 2; mt++) {
                const int Rm = wm + mt * 16 + grp;
                a[mt][0] = As[Rm][k0 + tig];
                a[mt][1] = As[Rm + 8][k0 + tig];
                a[mt][2] = As[Rm][k0 + tig + 4];
                a[mt][3] = As[Rm + 8][k0 + tig + 4];
            }
            float b[4][2];
            #pragma unroll
            for (int nt = 0; nt < 4; nt++) {
                const int Cn = wn + nt * 8 + grp;
                b[nt][0] = Bs[k0 + tig][Cn];
                b[nt][1] = Bs[k0 + tig + 4][Cn];
            }
            #pragma unroll
            for (int mt = 0; mt < 2; mt++)
                #pragma unroll
                for (int nt = 0; nt < 4; nt++)
                    mma_tf32(acc[mt][nt], a[mt][0], a[mt][1], a[mt][2], a[mt][3],
                             b[nt][0], b[nt][1]);
        }
        __syncthreads();
    }

    #pragma unroll
    for (int mt = 0; mt < 2; mt++) {
        #pragma unroll
        for (int half = 0; half < 2; half++) {
            const int m = m0 + wm + mt * 16 + grp + half * 8;
            #pragma unroll
            for (int nt = 0; nt < 4; nt++) {
                const int n = n0 + wn + nt * 8 + 2 * tig;
                float bb0 = bias[n], bb1 = bias[n + 1];
                float v0 = acc[mt][nt][half * 2 + 0] + bb0;
                float v1 = acc[mt][nt][half * 2 + 1] + bb1;
                *(float2*)(out + (size_t)m * 192 + n) = make_float2(v0, v1);
            }
        }
    }
}

// =====================================================================
extern "C" void kernel_launch(void* const* d_in, const int* in_sizes, int n_in,
                              void* d_out, int out_size)
{
    const float* x          = (const float*)d_in[0];
    const float* mask       = (const float*)d_in[1];
    const float* w_qkv      = (const float*)d_in[2];
    const float* w_proj     = (const float*)d_in[3];
    const float* b_proj     = (const float*)d_in[4];
    const float* bias_table = (const float*)d_in[5];
    float* out = (float*)d_out;

    cudaFuncSetAttribute(attn_kernel,
                         cudaFuncAttributeMaxDynamicSharedMemorySize, ATTN_SMEM);

    dim3 g1(MROWS / 128, 576 / 64);
    qkv_gemm<<<g1, 256>>>(x, w_qkv);

    bias_kernel<<<(WTYPES * HEADS * PT * PT + 255) / 256, 256>>>(bias_table);

    attn_kernel<<<WNUM * HEADS, 288, ATTN_SMEM>>>(mask);

    dim3 g2(MROWS / 128, 192 / 64);
    proj_gemm<<<g2, 256>>>(w_proj, b_proj, out);
}

// round 3
// speedup vs baseline: 3.1309x; 2.1636x over previous
#include <cuda_runtime.h>
#include <cuda_fp16.h>
#include <math.h>

// ---------------- static problem config ----------------
#define PT     144
#define DIMV   192
#define HEADS  6
#define DH     32
#define WNUM   960
#define MWIN   15
#define WTYPES 64
#define MROWS  (WNUM*PT)
#define QK_SCALE 0.17677669529663687f

// ---------------- device scratch (allocation-free rule) ----------------
__device__ __half g_qh[WNUM*HEADS*PT*DH];
__device__ __half g_kh[WNUM*HEADS*PT*DH];
__device__ __half g_vh[WNUM*HEADS*PT*DH];
__device__ __half g_aoh[(size_t)MROWS*DIMV];
__device__ __half g_biash[(size_t)WTYPES*HEADS*PT*PT];

// ---------------- helpers ----------------
__device__ __forceinline__ unsigned smaddr(const void* p) {
    return (unsigned)__cvta_generic_to_shared(p);
}
__device__ __forceinline__ void ldsm_x4(unsigned &r0, unsigned &r1,
                                        unsigned &r2, unsigned &r3, unsigned a) {
    asm volatile("ldmatrix.sync.aligned.m8n8.x4.shared.b16 {%0,%1,%2,%3}, [%4];"
                 : "=r"(r0), "=r"(r1), "=r"(r2), "=r"(r3) : "r"(a));
}
__device__ __forceinline__ void ldsm_x2t(unsigned &r0, unsigned &r1, unsigned a) {
    asm volatile("ldmatrix.sync.aligned.m8n8.x2.trans.shared.b16 {%0,%1}, [%2];"
                 : "=r"(r0), "=r"(r1) : "r"(a));
}
__device__ __forceinline__ void mma16816(float c[4],
                                         unsigned a0, unsigned a1, unsigned a2, unsigned a3,
                                         unsigned b0, unsigned b1) {
    asm volatile("mma.sync.aligned.m16n8k16.row.col.f32.f16.f16.f32 "
                 "{%0,%1,%2,%3}, {%4,%5,%6,%7}, {%8,%9}, {%0,%1,%2,%3};"
                 : "+f"(c[0]), "+f"(c[1]), "+f"(c[2]), "+f"(c[3])
                 : "r"(a0), "r"(a1), "r"(a2), "r"(a3), "r"(b0), "r"(b1));
}
__device__ __forceinline__ unsigned packh2(float a, float b) {
    __half2 t = __floats2half2_rn(a, b);
    return *(unsigned*)&t;
}

// =====================================================================
// Kernel 1: QKV GEMM fp16 TC. C(138240,576) = x @ w_qkv; scatter epilogue.
// Block 128x64, BK=32, 256 thr / 8 warps (4x2), warp 32x32.
// =====================================================================
__global__ __launch_bounds__(256) void qkv_gemm(const float* __restrict__ x,
                                                const float* __restrict__ w)
{
    __shared__ __half As[128][40];
    __shared__ __half Bs[32][72];

    const int m0 = blockIdx.x * 128;
    const int n0 = blockIdx.y * 64;
    const int tid = threadIdx.x;
    const int wid = tid >> 5, lane = tid & 31;
    const int grp = lane >> 2, tig = lane & 3;
    const int wm = (wid >> 1) * 32, wn = (wid & 1) * 32;

    float acc[2][4][4];
    #pragma unroll
    for (int mt = 0; mt < 2; mt++)
        #pragma unroll
        for (int nt = 0; nt < 4; nt++)
            #pragma unroll
            for (int i = 0; i < 4; i++) acc[mt][nt][i] = 0.f;

    for (int kt = 0; kt < 192; kt += 32) {
        #pragma unroll
        for (int i = 0; i < 4; i++) {
            const int row = (tid >> 3) + i * 32;
            const int c4  = (tid & 7) * 4;
            float4 a = *(const float4*)(x + (size_t)(m0 + row) * 192 + kt + c4);
            *(__half2*)&As[row][c4]     = __floats2half2_rn(a.x, a.y);
            *(__half2*)&As[row][c4 + 2] = __floats2half2_rn(a.z, a.w);
        }
        {
            const int kr = tid >> 3;
            const int nc = (tid & 7) * 8;
            #pragma unroll
            for (int j = 0; j < 2; j++) {
                float4 b = *(const float4*)(w + (size_t)(kt + kr) * 576 + n0 + nc + j * 4);
                *(__half2*)&Bs[kr][nc + j*4]     = __floats2half2_rn(b.x, b.y);
                *(__half2*)&Bs[kr][nc + j*4 + 2] = __floats2half2_rn(b.z, b.w);
            }
        }
        __syncthreads();

        #pragma unroll
        for (int k0 = 0; k0 < 32; k0 += 16) {
            unsigned au[2][4];
            #pragma unroll
            for (int mt = 0; mt < 2; mt++)
                ldsm_x4(au[mt][0], au[mt][1], au[mt][2], au[mt][3],
                        smaddr(&As[wm + mt*16 + (lane & 15)][k0 + ((lane >> 4) << 3)]));
            unsigned bu[4][2];
            #pragma unroll
            for (int nt = 0; nt < 4; nt++)
                ldsm_x2t(bu[nt][0], bu[nt][1],
                         smaddr(&Bs[k0 + (lane & 15)][wn + nt*8]));
            #pragma unroll
            for (int mt = 0; mt < 2; mt++)
                #pragma unroll
                for (int nt = 0; nt < 4; nt++)
                    mma16816(acc[mt][nt], au[mt][0], au[mt][1], au[mt][2], au[mt][3],
                             bu[nt][0], bu[nt][1]);
        }
        __syncthreads();
    }

    #pragma unroll
    for (int mt = 0; mt < 2; mt++) {
        #pragma unroll
        for (int hh = 0; hh < 2; hh++) {
            const int m   = m0 + wm + mt*16 + grp + hh*8;
            const int wnn = m / PT;
            const int p   = m - wnn * PT;
            #pragma unroll
            for (int nt = 0; nt < 4; nt++) {
                const int n     = n0 + wn + nt*8 + 2*tig;
                const int three = n / 192;
                const int rem   = n - three * 192;
                const int head  = rem >> 5;
                const int d     = rem & 31;
                float v0 = acc[mt][nt][hh*2 + 0];
                float v1 = acc[mt][nt][hh*2 + 1];
                const size_t di = (((size_t)wnn * HEADS + head) * PT + p) * DH + d;
                if (three == 0) {
                    __half2 t = __floats2half2_rn(v0 * QK_SCALE, v1 * QK_SCALE);
                    *(__half2*)(g_qh + di) = t;
                } else if (three == 1) {
                    *(__half2*)(g_kh + di) = __floats2half2_rn(v0, v1);
                } else {
                    *(__half2*)(g_vh + di) = __floats2half2_rn(v0, v1);
                }
            }
        }
    }
}

// =====================================================================
// Kernel 2: earth-bias gather into contiguous (WT, H, P, P), fp16
// =====================================================================
__global__ void bias_kernel(const float* __restrict__ table)
{
    int t = blockIdx.x * 256 + threadIdx.x;
    if (t >= WTYPES * HEADS * PT * PT) return;
    int j  = t % PT;
    int r1 = t / PT;
    int i  = r1 % PT;
    int r2 = r1 / PT;
    int h  = r2 % HEADS;
    int wt = r2 / HEADS;

    int zi = i / 72, hi = (i / 12) % 6, wi = i % 12;
    int zj = j / 72, hj = (j / 12) % 6, wj = j % 12;
    int idx = 828 * (zi + 2 * zj) + 23 * (hi + 6 * hj) + (wi - wj + 11);

    g_biash[t] = __float2half(table[(size_t)idx * (WTYPES * HEADS) + wt * HEADS + h]);
}

// =====================================================================
// Kernel 3: attention per (window, head). 288 thr / 9 warps.
// Warp owns 16 rows; S never hits smem; ONE __syncthreads total.
// =====================================================================
__global__ __launch_bounds__(288) void attn_kernel(const float* __restrict__ mask)
{
    __shared__ __half Qs[PT][40];
    __shared__ __half Ks[PT][40];
    __shared__ __half Vs[PT][40];

    const int wn = blockIdx.x / HEADS;
    const int h  = blockIdx.x - wn * HEADS;
    const int tid = threadIdx.x;
    const int wid = tid >> 5, lane = tid & 31;
    const int grp = lane >> 2, tig = lane & 3;

    const size_t base = (size_t)(wn * HEADS + h) * (PT * DH);
    const unsigned* qg = (const unsigned*)(g_qh + base);
    const unsigned* kg = (const unsigned*)(g_kh + base);
    const unsigned* vg = (const unsigned*)(g_vh + base);
    for (int i = tid; i < PT * DH / 2; i += 288) {
        const int r = i >> 4, c = (i & 15) * 2;
        *(unsigned*)&Qs[r][c] = qg[i];
        *(unsigned*)&Ks[r][c] = kg[i];
        *(unsigned*)&Vs[r][c] = vg[i];
    }
    __syncthreads();

    const int m0 = wid * 16;

    // ---- phase 1: S = Q K^T (A: ldmatrix, B: direct half2 from K rows) ----
    float acc[18][4];
    #pragma unroll
    for (int nt = 0; nt < 18; nt++)
        #pragma unroll
        for (int i = 0; i < 4; i++) acc[nt][i] = 0.f;

    #pragma unroll
    for (int k0 = 0; k0 < 32; k0 += 16) {
        unsigned a0, a1, a2, a3;
        ldsm_x4(a0, a1, a2, a3,
                smaddr(&Qs[m0 + (lane & 15)][k0 + ((lane >> 4) << 3)]));
        #pragma unroll
        for (int nt = 0; nt < 18; nt++) {
            unsigned b0 = *(const unsigned*)&Ks[nt*8 + grp][k0 + 2*tig];
            unsigned b1 = *(const unsigned*)&Ks[nt*8 + grp][k0 + 2*tig + 8];
            mma16816(acc[nt], a0, a1, a2, a3, b0, b1);
        }
    }

    // ---- phase 2: bias + mask + softmax (register-resident) ----
    const int r0 = m0 + grp, r1 = r0 + 8;
    const __half* bp = g_biash + (size_t)((wn / MWIN) * HEADS + h) * PT * PT;
    const float*  mp = mask + (size_t)wn * PT * PT;

    float mx0 = -1e30f, mx1 = -1e30f;
    #pragma unroll
    for (int nt = 0; nt < 18; nt++) {
        const int c = nt*8 + 2*tig;
        float2 b0 = __half22float2(*(const __half2*)(bp + r0*PT + c));
        float2 b1 = __half22float2(*(const __half2*)(bp + r1*PT + c));
        float2 k0v = *(const float2*)(mp + r0*PT + c);
        float2 k1v = *(const float2*)(mp + r1*PT + c);
        acc[nt][0] += b0.x + k0v.x;  acc[nt][1] += b0.y + k0v.y;
        acc[nt][2] += b1.x + k1v.x;  acc[nt][3] += b1.y + k1v.y;
        mx0 = fmaxf(mx0, fmaxf(acc[nt][0], acc[nt][1]));
        mx1 = fmaxf(mx1, fmaxf(acc[nt][2], acc[nt][3]));
    }
    mx0 = fmaxf(mx0, __shfl_xor_sync(0xffffffffu, mx0, 1));
    mx0 = fmaxf(mx0, __shfl_xor_sync(0xffffffffu, mx0, 2));
    mx1 = fmaxf(mx1, __shfl_xor_sync(0xffffffffu, mx1, 1));
    mx1 = fmaxf(mx1, __shfl_xor_sync(0xffffffffu, mx1, 2));

    float s0 = 0.f, s1 = 0.f;
    #pragma unroll
    for (int nt = 0; nt < 18; nt++) {
        acc[nt][0] = __expf(acc[nt][0] - mx0);
        acc[nt][1] = __expf(acc[nt][1] - mx0);
        acc[nt][2] = __expf(acc[nt][2] - mx1);
        acc[nt][3] = __expf(acc[nt][3] - mx1);
        s0 += acc[nt][0] + acc[nt][1];
        s1 += acc[nt][2] + acc[nt][3];
    }
    s0 += __shfl_xor_sync(0xffffffffu, s0, 1);
    s0 += __shfl_xor_sync(0xffffffffu, s0, 2);
    s1 += __shfl_xor_sync(0xffffffffu, s1, 1);
    s1 += __shfl_xor_sync(0xffffffffu, s1, 2);
    const float inv0 = 1.f / s0, inv1 = 1.f / s1;

    unsigned ph0[18], ph1[18];   // P packed exactly as phase-3 A fragments
    #pragma unroll
    for (int nt = 0; nt < 18; nt++) {
        ph0[nt] = packh2(acc[nt][0] * inv0, acc[nt][1] * inv0);
        ph1[nt] = packh2(acc[nt][2] * inv1, acc[nt][3] * inv1);
    }

    // ---- phase 3: O = P V ----
    float oacc[4][4];
    #pragma unroll
    for (int nt = 0; nt < 4; nt++)
        #pragma unroll
        for (int i = 0; i < 4; i++) oacc[nt][i] = 0.f;

    #pragma unroll
    for (int kt = 0; kt < 9; kt++) {
        unsigned b0, b1;
        #pragma unroll
        for (int nt = 0; nt < 4; nt++) {
            ldsm_x2t(b0, b1, smaddr(&Vs[kt*16 + (lane & 15)][nt*8]));
            mma16816(oacc[nt], ph0[2*kt], ph1[2*kt], ph0[2*kt + 1], ph1[2*kt + 1], b0, b1);
        }
    }

    #pragma unroll
    for (int hh = 0; hh < 2; hh++) {
        const int row = m0 + grp + hh*8;
        __half* o = g_aoh + ((size_t)(wn * PT + row)) * DIMV + h * DH;
        #pragma unroll
        for (int nt = 0; nt < 4; nt++) {
            const int col = nt*8 + 2*tig;
            *(__half2*)(o + col) = __floats2half2_rn(oacc[nt][hh*2], oacc[nt][hh*2 + 1]);
        }
    }
}

// =====================================================================
// Kernel 4: proj GEMM fp16 TC. out(138240,192) = g_ao @ w_proj + b_proj
// =====================================================================
__global__ __launch_bounds__(256) void proj_gemm(const float* __restrict__ w,
                                                 const float* __restrict__ bias,
                                                 float* __restrict__ out)
{
    __shared__ __half As[128][40];
    __shared__ __half Bs[32][72];

    const int m0 = blockIdx.x * 128;
    const int n0 = blockIdx.y * 64;
    const int tid = threadIdx.x;
    const int wid = tid >> 5, lane = tid & 31;
    const int grp = lane >> 2, tig = lane & 3;
    const int wm = (wid >> 1) * 32, wn = (wid & 1) * 32;

    float acc[2][4][4];
    #pragma unroll
    for (int mt = 0; mt < 2; mt++)
        #pragma unroll
        for (int nt = 0; nt < 4; nt++)
            #pragma unroll
            for (int i = 0; i < 4; i++) acc[mt][nt][i] = 0.f;

    for (int kt = 0; kt < 192; kt += 32) {
        #pragma unroll
        for (int i = 0; i < 4; i++) {
            const int row = (tid >> 3) + i * 32;
            const int c4  = (tid & 7) * 4;
            uint2 v = *(const uint2*)(g_aoh + (size_t)(m0 + row) * 192 + kt + c4);
            *(uint2*)&As[row][c4] = v;
        }
        {
            const int kr = tid >> 3;
            const int nc = (tid & 7) * 8;
            #pragma unroll
            for (int j = 0; j < 2; j++) {
                float4 b = *(const float4*)(w + (size_t)(kt + kr) * 192 + n0 + nc + j * 4);
                *(__half2*)&Bs[kr][nc + j*4]     = __floats2half2_rn(b.x, b.y);
                *(__half2*)&Bs[kr][nc + j*4 + 2] = __floats2half2_rn(b.z, b.w);
            }
        }
        __syncthreads();

        #pragma unroll
        for (int k0 = 0; k0 < 32; k0 += 16) {
            unsigned au[2][4];
            #pragma unroll
            for (int mt = 0; mt < 2; mt++)
                ldsm_x4(au[mt][0], au[mt][1], au[mt][2], au[mt][3],
                        smaddr(&As[wm + mt*16 + (lane & 15)][k0 + ((lane >> 4) << 3)]));
            unsigned bu[4][2];
            #pragma unroll
            for (int nt = 0; nt < 4; nt++)
                ldsm_x2t(bu[nt][0], bu[nt][1],
                         smaddr(&Bs[k0 + (lane & 15)][wn + nt*8]));
            #pragma unroll
            for (int mt = 0; mt < 2; mt++)
                #pragma unroll
                for (int nt = 0; nt < 4; nt++)
                    mma16816(acc[mt][nt], au[mt][0], au[mt][1], au[mt][2], au[mt][3],
                             bu[nt][0], bu[nt][1]);
        }
        __syncthreads();
    }

    #pragma unroll
    for (int mt = 0; mt < 2; mt++) {
        #pragma unroll
        for (int hh = 0; hh < 2; hh++) {
            const int m = m0 + wm + mt*16 + grp + hh*8;
            #pragma unroll
            for (int nt = 0; nt < 4; nt++) {
                const int n = n0 + wn + nt*8 + 2*tig;
                float v0 = acc[mt][nt][hh*2 + 0] + bias[n];
                float v1 = acc[mt][nt][hh*2 + 1] + bias[n + 1];
                *(float2*)(out + (size_t)m * 192 + n) = make_float2(v0, v1);
            }
        }
    }
}

// =====================================================================
extern "C" void kernel_launch(void* const* d_in, const int* in_sizes, int n_in,
                              void* d_out, int out_size)
{
    const float* x          = (const float*)d_in[0];
    const float* mask       = (const float*)d_in[1];
    const float* w_qkv      = (const float*)d_in[2];
    const float* w_proj     = (const float*)d_in[3];
    const float* b_proj     = (const float*)d_in[4];
    const float* bias_table = (const float*)d_in[5];
    float* out = (float*)d_out;

    dim3 g1(MROWS / 128, 576 / 64);
    qkv_gemm<<<g1, 256>>>(x, w_qkv);

    bias_kernel<<<(WTYPES * HEADS * PT * PT + 255) / 256, 256>>>(bias_table);

    attn_kernel<<<WNUM * HEADS, 288>>>(mask);

    dim3 g2(MROWS / 128, 192 / 64);
    proj_gemm<<<g2, 256>>>(w_proj, b_proj, out);
}